// round 8
// baseline (speedup 1.0000x reference)
#include <cuda_runtime.h>
#include <cstddef>
#include <cstdint>

// Sizes: B=64, S=1024, E=256 (== proj dim), H=1024, G=4*H=4096
#define NB 64
#define NS 1024
#define NE 256
#define NH 1024
#define NG 4096
#define NBLK 148     // phase-1 blocks (all co-resident, 1/SM)
#define RBLK 128     // recurrence blocks (64 per direction)

// ---------------- device scratch (static: no runtime allocation) ------------
__device__ float g_xg[2][(size_t)NS * NB * NG];  // 2 x 1 GiB  xg [dir][s][b][g]
__device__ float g_h[2][2][NB * NE];             // [parity][dir][b*256+p]
__device__ float g_a[2][NB * NH];                // [dir][b*1024+j]
__device__ unsigned g_ctr[4];                    // [0]=grid, [1]=dir0, [2]=dir1

__device__ __forceinline__ float sigf(float x) { return 1.0f / (1.0f + __expf(-x)); }
__device__ __forceinline__ float tanh_f(float x) {
    float e = __expf(2.0f * x);
    return 1.0f - 2.0f / (e + 1.0f);
}

// Device-scope barrier: monotonic counter. Release = threadfence + atomicAdd;
// acquire = ld.acquire.gpu poll + __syncthreads broadcast.
__device__ __forceinline__ void gbar(unsigned* c, unsigned target) {
    __syncthreads();
    if (threadIdx.x == 0) {
        __threadfence();
        atomicAdd(c, 1u);
        unsigned v;
        do {
            asm volatile("ld.global.acquire.gpu.u32 %0, [%1];"
                         : "=r"(v) : "l"(c) : "memory");
        } while (v < target);
    }
    __syncthreads();
}

// 64x64x32 FMA core, k-major smem (stride 68 floats, 16B-aligned rows).
__device__ __forceinline__ void mm32(const float* __restrict__ A,
                                     const float* __restrict__ B,
                                     int tr, int tc, float acc[4][4]) {
#pragma unroll
    for (int kk = 0; kk < 32; kk++) {
        float4 a4 = *(const float4*)&A[kk * 68 + tr * 4];
        float4 b4 = *(const float4*)&B[kk * 68 + tc * 4];
        float av[4] = {a4.x, a4.y, a4.z, a4.w};
        float bv[4] = {b4.x, b4.y, b4.z, b4.w};
#pragma unroll
        for (int r = 0; r < 4; r++)
#pragma unroll
            for (int q = 0; q < 4; q++) acc[r][q] += av[r] * bv[q];
    }
}

// --------------------------- init: zero state + counters --------------------
__global__ void init_kernel() {
    int i = blockIdx.x * blockDim.x + threadIdx.x;   // 64 x 512 = 32768
    if (i < 4) g_ctr[i] = 0u;
    if (i < 2 * NB * NE) (&g_h[0][0][0])[i] = 0.0f;  // parity-0 h, both dirs
}

// --------------------------- the whole network ------------------------------
__global__ __launch_bounds__(512, 1) void lstm_kernel(
    const float* __restrict__ x,
    const float* __restrict__ Wihf, const float* __restrict__ Whhf,
    const float* __restrict__ bihf, const float* __restrict__ bhhf,
    const float* __restrict__ Whrf,
    const float* __restrict__ Wihb, const float* __restrict__ Whhb,
    const float* __restrict__ bihb, const float* __restrict__ bhhb,
    const float* __restrict__ Whrb,
    float* __restrict__ out)
{
    __shared__ float As[2][32 * 68];
    __shared__ float Bs[2][32 * 68];
    __shared__ float gs[64 * 68];

    const int bid = blockIdx.x;
    const int tid = threadIdx.x;
    const int kg  = tid >> 8;          // K-group 0/1
    const int t2  = tid & 255;
    const int tr  = t2 >> 4, tc = t2 & 15;
    float* Ak = &As[kg][0];
    float* Bk = &Bs[kg][0];

    // ---------------- phase 1: xg = x @ W_ih^T + (b_ih + b_hh) -------------
    // 131072 tiles of 64b x 64g x K256, stolen round-robin by 148 blocks.
    {
        const int total_tiles = 2 * 64 * NS;
        for (int tile = bid; tile < total_tiles; tile += NBLK) {
            const int s      = tile & (NS - 1);
            const int stripe = tile >> 10;         // 0..127
            const int dp     = stripe >> 6;
            const int n0     = (stripe & 63) << 6;
            const float* __restrict__ W  = dp ? Wihb : Wihf;
            const float* __restrict__ bi = dp ? bihb : bihf;
            const float* __restrict__ bh = dp ? bhhb : bhhf;
            float* __restrict__ xo = g_xg[dp];

            float acc[4][4];
#pragma unroll
            for (int r = 0; r < 4; r++)
#pragma unroll
                for (int q = 0; q < 4; q++) acc[r][q] = 0.0f;

            for (int rr = 0; rr < 4; rr++) {
                const int k0 = rr * 64 + kg * 32;
#pragma unroll
                for (int i = 0; i < 2; i++) {
                    int f = t2 + i * 256;
                    int r = f >> 3;
                    int kq = (f & 7) << 2;
                    float4 va = *(const float4*)&x[((size_t)r * NS + s) * NE + k0 + kq];
                    Ak[(kq + 0) * 68 + r] = va.x; Ak[(kq + 1) * 68 + r] = va.y;
                    Ak[(kq + 2) * 68 + r] = va.z; Ak[(kq + 3) * 68 + r] = va.w;
                    float4 vb = *(const float4*)&W[(size_t)(n0 + r) * NE + k0 + kq];
                    Bk[(kq + 0) * 68 + r] = vb.x; Bk[(kq + 1) * 68 + r] = vb.y;
                    Bk[(kq + 2) * 68 + r] = vb.z; Bk[(kq + 3) * 68 + r] = vb.w;
                }
                __syncthreads();
                mm32(Ak, Bk, tr, tc, acc);
                __syncthreads();
            }
            if (kg == 1) {
#pragma unroll
                for (int r = 0; r < 4; r++)
#pragma unroll
                    for (int q = 0; q < 4; q++)
                        gs[(tc * 4 + q) * 68 + tr * 4 + r] = acc[r][q];
            }
            __syncthreads();
            if (kg == 0) {
                float4 bia = *(const float4*)&bi[n0 + tc * 4];
                float4 bha = *(const float4*)&bh[n0 + tc * 4];
                float bias[4] = {bia.x + bha.x, bia.y + bha.y,
                                 bia.z + bha.z, bia.w + bha.w};
#pragma unroll
                for (int r = 0; r < 4; r++) {
                    int b = tr * 4 + r;
                    float4 o;
                    o.x = acc[r][0] + gs[(tc * 4 + 0) * 68 + b] + bias[0];
                    o.y = acc[r][1] + gs[(tc * 4 + 1) * 68 + b] + bias[1];
                    o.z = acc[r][2] + gs[(tc * 4 + 2) * 68 + b] + bias[2];
                    o.w = acc[r][3] + gs[(tc * 4 + 3) * 68 + b] + bias[3];
                    __stcs((float4*)&xo[((size_t)s * NB + b) * NG + n0 + tc * 4], o);
                }
            }
            __syncthreads();
        }
    }
    gbar(&g_ctr[0], (unsigned)NBLK);
    if (bid >= RBLK) return;

    // ---------------- phase 2: the recurrence -------------------------------
    const int dir = bid >> 6;
    const int w   = bid & 63;
    const float* __restrict__ Whh = dir ? Whhb : Whhf;
    const float* __restrict__ Whr = dir ? Whrb : Whrf;
    const float* __restrict__ xg  = g_xg[dir];
    unsigned* ctr = &g_ctr[1 + dir];

    const int j0    = w << 4;            // gates: 16 hidden units
    const int p0    = (w >> 4) << 6;     // proj: output col tile
    const int kbase = (w & 15) << 6;     // proj: K slice

    float creg[2] = {0.0f, 0.0f};        // cell state in registers

    for (int t = 0; t < NS; t++) {
        const int par = t & 1;
        const float* __restrict__ h = g_h[par][dir];
        float* __restrict__ hn = g_h[par ^ 1][dir];
        const int s_eff = dir ? (NS - 1 - t) : t;

        if (tid < 256) hn[w * 256 + tid] = 0.0f;

        // prefetch xg for this thread's rows (kg-split: kg0 rows 0-1, kg1 2-3)
        float4 xgv[2];
        {
            int cbase = tc * 4;
            int gcol = ((cbase >> 4) << 10) + j0 + (cbase & 15);
#pragma unroll
            for (int i = 0; i < 2; i++) {
                int b = tr * 4 + kg * 2 + i;
                xgv[i] = __ldcs((const float4*)&xg[((size_t)s_eff * NB + b) * NG + gcol]);
            }
        }

        // ---- gates GEMM: 64b x 64c, K=256 (split-K over kg) ---------------
        float acc[4][4];
#pragma unroll
        for (int r = 0; r < 4; r++)
#pragma unroll
            for (int q = 0; q < 4; q++) acc[r][q] = 0.0f;

        for (int rr = 0; rr < 4; rr++) {
            const int k0 = rr * 64 + kg * 32;
#pragma unroll
            for (int i = 0; i < 2; i++) {
                int f = t2 + i * 256;
                int r = f >> 3;
                int kq = (f & 7) << 2;
                float4 va = __ldcg((const float4*)&h[r * NE + k0 + kq]);
                Ak[(kq + 0) * 68 + r] = va.x; Ak[(kq + 1) * 68 + r] = va.y;
                Ak[(kq + 2) * 68 + r] = va.z; Ak[(kq + 3) * 68 + r] = va.w;
                int g = ((r >> 4) << 10) + j0 + (r & 15);
                float4 vb = *(const float4*)&Whh[(size_t)g * NE + k0 + kq];
                Bk[(kq + 0) * 68 + r] = vb.x; Bk[(kq + 1) * 68 + r] = vb.y;
                Bk[(kq + 2) * 68 + r] = vb.z; Bk[(kq + 3) * 68 + r] = vb.w;
            }
            __syncthreads();
            mm32(Ak, Bk, tr, tc, acc);
            __syncthreads();
        }
        // fold in xg (each kg covers its 2 rows)
#pragma unroll
        for (int i = 0; i < 2; i++) {
            int r = kg * 2 + i;
            acc[r][0] += xgv[i].x; acc[r][1] += xgv[i].y;
            acc[r][2] += xgv[i].z; acc[r][3] += xgv[i].w;
        }
        if (kg == 1) {
#pragma unroll
            for (int r = 0; r < 4; r++)
#pragma unroll
                for (int q = 0; q < 4; q++)
                    gs[(tc * 4 + q) * 68 + tr * 4 + r] = acc[r][q];
        }
        __syncthreads();
        if (kg == 0) {
#pragma unroll
            for (int r = 0; r < 4; r++)
#pragma unroll
                for (int q = 0; q < 4; q++)
                    gs[(tc * 4 + q) * 68 + tr * 4 + r] += acc[r][q];
        }
        __syncthreads();

        // ---- cell update (c in registers), 512 threads x 2 pairs ----------
#pragma unroll
        for (int i = 0; i < 2; i++) {
            int m = tid + i * 512;            // 0..1023
            int jl = m & 15, b = m >> 4;
            float gi = gs[( 0 + jl) * 68 + b];
            float gf = gs[(16 + jl) * 68 + b];
            float gg = gs[(32 + jl) * 68 + b];
            float go = gs[(48 + jl) * 68 + b];
            float cn = sigf(gf) * creg[i] + sigf(gi) * tanh_f(gg);
            creg[i] = cn;
            g_a[dir][b * NH + j0 + jl] = sigf(go) * tanh_f(cn);
        }

        gbar(ctr, (unsigned)(2 * t + 1) * 64u);   // all a complete

        // ---- projection: hn += a[:,kslice] @ Whr_tile^T -------------------
        float pacc[4][4];
#pragma unroll
        for (int r = 0; r < 4; r++)
#pragma unroll
            for (int q = 0; q < 4; q++) pacc[r][q] = 0.0f;
        {
            const int k0 = kbase + kg * 32;
#pragma unroll
            for (int i = 0; i < 2; i++) {
                int f = t2 + i * 256;
                int r = f >> 3;
                int kq = (f & 7) << 2;
                float4 va = __ldcg((const float4*)&g_a[dir][r * NH + k0 + kq]);
                Ak[(kq + 0) * 68 + r] = va.x; Ak[(kq + 1) * 68 + r] = va.y;
                Ak[(kq + 2) * 68 + r] = va.z; Ak[(kq + 3) * 68 + r] = va.w;
                float4 vb = *(const float4*)&Whr[(size_t)(p0 + r) * NH + k0 + kq];
                Bk[(kq + 0) * 68 + r] = vb.x; Bk[(kq + 1) * 68 + r] = vb.y;
                Bk[(kq + 2) * 68 + r] = vb.z; Bk[(kq + 3) * 68 + r] = vb.w;
            }
            __syncthreads();
            mm32(Ak, Bk, tr, tc, pacc);
            __syncthreads();
        }
        if (kg == 1) {
#pragma unroll
            for (int r = 0; r < 4; r++)
#pragma unroll
                for (int q = 0; q < 4; q++)
                    gs[(tc * 4 + q) * 68 + tr * 4 + r] = pacc[r][q];
        }
        __syncthreads();
        if (kg == 0) {
#pragma unroll
            for (int r = 0; r < 4; r++) {
                int b = tr * 4 + r;
#pragma unroll
                for (int q = 0; q < 4; q++)
                    atomicAdd(&hn[b * NE + p0 + tc * 4 + q],
                              pacc[r][q] + gs[(tc * 4 + q) * 68 + b]);
            }
        }

        gbar(ctr, (unsigned)(2 * t + 2) * 64u);   // h_next complete

        // ---- stream this step's h to output (batch w, coalesced) ----------
        if (tid < 256) {
            float v = __ldcg(&hn[w * 256 + tid]);
            out[((size_t)w * NS + s_eff) * (2 * NE) + dir * NE + tid] = v;
        }
    }
}

// ----------------------------- launcher -------------------------------------
extern "C" void kernel_launch(void* const* d_in, const int* in_sizes, int n_in,
                              void* d_out, int out_size) {
    (void)in_sizes; (void)n_in; (void)out_size;
    const float* x    = (const float*)d_in[0];
    const float* Wihf = (const float*)d_in[1];
    const float* Whhf = (const float*)d_in[2];
    const float* bihf = (const float*)d_in[3];
    const float* bhhf = (const float*)d_in[4];
    const float* Whrf = (const float*)d_in[5];
    const float* Wihb = (const float*)d_in[6];
    const float* Whhb = (const float*)d_in[7];
    const float* bihb = (const float*)d_in[8];
    const float* bhhb = (const float*)d_in[9];
    const float* Whrb = (const float*)d_in[10];
    float* out = (float*)d_out;

    init_kernel<<<64, 512>>>();
    lstm_kernel<<<NBLK, 512>>>(x, Wihf, Whhf, bihf, bhhf, Whrf,
                               Wihb, Whhb, bihb, bhhb, Whrb, out);
}

// round 9
// speedup vs baseline: 1.9339x; 1.9339x over previous
#include <cuda_runtime.h>
#include <cstddef>
#include <cstdint>

// Sizes: B=64, S=1024, E=256 (== proj dim), H=1024, G=4*H=4096
#define NB 64
#define NS 1024
#define NE 256
#define NH 1024
#define NG 4096
#define NBLK 148     // phase-1 blocks (all co-resident, 1/SM)
#define RBLK 128     // recurrence blocks (64 per direction)

// ---------------- device scratch (static: no runtime allocation) ------------
__device__ float g_xg[2][(size_t)NS * NB * NG];  // 2 x 1 GiB  xg [dir][s][b][g]
__device__ float g_h[2][2][NB * NE];             // [parity][dir][b*256+p]
__device__ float g_a[2][NB * NH];                // [dir][b*1024+j]
__device__ unsigned g_ctr[4];                    // [0]=grid, [1]=dir0, [2]=dir1

__device__ __forceinline__ float sigf(float x) { return 1.0f / (1.0f + __expf(-x)); }
__device__ __forceinline__ float tanh_f(float x) {
    float e = __expf(2.0f * x);
    return 1.0f - 2.0f / (e + 1.0f);
}

// tf32 conversion of a float4 -> 4 tf32 bit-patterns
__device__ __forceinline__ uint4 cvt4(float4 v) {
    uint4 u;
    asm("cvt.rna.tf32.f32 %0, %1;" : "=r"(u.x) : "f"(v.x));
    asm("cvt.rna.tf32.f32 %0, %1;" : "=r"(u.y) : "f"(v.y));
    asm("cvt.rna.tf32.f32 %0, %1;" : "=r"(u.z) : "f"(v.z));
    asm("cvt.rna.tf32.f32 %0, %1;" : "=r"(u.w) : "f"(v.w));
    return u;
}

// m16n8k8 tf32 MMA, acc += A*B
__device__ __forceinline__ void mma_tf32(float* acc,
                                         uint32_t a0, uint32_t a1, uint32_t a2, uint32_t a3,
                                         uint32_t b0, uint32_t b1) {
    asm volatile(
        "mma.sync.aligned.m16n8k8.row.col.f32.tf32.tf32.f32 "
        "{%0,%1,%2,%3}, {%4,%5,%6,%7}, {%8,%9}, {%0,%1,%2,%3};"
        : "+f"(acc[0]), "+f"(acc[1]), "+f"(acc[2]), "+f"(acc[3])
        : "r"(a0), "r"(a1), "r"(a2), "r"(a3), "r"(b0), "r"(b1));
}

// One 32-wide K chunk of warp-level MMA. A/B in smem row-major [row][36].
// Warp computes m16 (rows mg..mg+15) x (nts*8) cols starting at ngb.
template <int NTS>
__device__ __forceinline__ void warp_mma_chunk(const uint32_t* __restrict__ Au,
                                               const uint32_t* __restrict__ Bu,
                                               int mg, int ngb, int l,
                                               float acc[][4]) {
#pragma unroll
    for (int ks = 0; ks < 4; ks++) {
        int k0 = ks * 8 + (l & 3);
        int ra = (mg + (l >> 2)) * 36 + k0;
        uint32_t a0 = Au[ra];
        uint32_t a1 = Au[ra + 8 * 36];
        uint32_t a2 = Au[ra + 4];
        uint32_t a3 = Au[ra + 8 * 36 + 4];
#pragma unroll
        for (int nt = 0; nt < NTS; nt++) {
            int rb = (ngb + nt * 8 + (l >> 2)) * 36 + k0;
            mma_tf32(acc[nt], a0, a1, a2, a3, Bu[rb], Bu[rb + 4]);
        }
    }
}

// Device-scope barrier: monotonic counter.
__device__ __forceinline__ void gbar(unsigned* c, unsigned target) {
    __syncthreads();
    if (threadIdx.x == 0) {
        __threadfence();
        atomicAdd(c, 1u);
        unsigned v;
        do {
            asm volatile("ld.global.acquire.gpu.u32 %0, [%1];"
                         : "=r"(v) : "l"(c) : "memory");
        } while (v < target);
    }
    __syncthreads();
}

// --------------------------- init: zero state + counters --------------------
__global__ void init_kernel() {
    int i = blockIdx.x * blockDim.x + threadIdx.x;   // 64 x 512
    if (i < 4) g_ctr[i] = 0u;
    if (i < 2 * NB * NE) (&g_h[0][0][0])[i] = 0.0f;
}

// --------------------------- the whole network ------------------------------
__global__ __launch_bounds__(512, 1) void lstm_kernel(
    const float* __restrict__ x,
    const float* __restrict__ Wihf, const float* __restrict__ Whhf,
    const float* __restrict__ bihf, const float* __restrict__ bhhf,
    const float* __restrict__ Whrf,
    const float* __restrict__ Wihb, const float* __restrict__ Whhb,
    const float* __restrict__ bihb, const float* __restrict__ bhhb,
    const float* __restrict__ Whrb,
    float* __restrict__ out)
{
    // pool: As[kg] at kg*2304, Bs[kg] at 4608+kg*2304 (floats). gs aliases pool.
    __shared__ __align__(16) float pool[4 * 2304];

    const int bid = blockIdx.x;
    const int tid = threadIdx.x;
    const int kg  = tid >> 8;          // K-group 0/1
    const int t2  = tid & 255;
    const int l   = tid & 31;
    const int wi  = t2 >> 5;           // warp-in-group 0..7
    const int mg  = (wi & 3) << 4;     // m16 group row base
    uint32_t* Au = (uint32_t*)(pool + kg * 2304);
    uint32_t* Bu = (uint32_t*)(pool + 4608 + kg * 2304);
    float* gs = pool;                  // [c*65 + r], used post-GEMM only

    // ---------------- phase 1: xg = x @ W_ih^T + (b_ih + b_hh) -------------
    {
        const int ngb = (wi >> 2) << 5;         // 0 or 32
        const int total_tiles = 2 * 64 * NS;
        for (int tile = bid; tile < total_tiles; tile += NBLK) {
            const int s      = tile & (NS - 1);
            const int stripe = tile >> 10;       // 0..127
            const int dp     = stripe >> 6;
            const int n0     = (stripe & 63) << 6;
            const float* __restrict__ W  = dp ? Wihb : Wihf;
            const float* __restrict__ bi = dp ? bihb : bihf;
            const float* __restrict__ bh = dp ? bhhb : bhhf;
            float* __restrict__ xo = g_xg[dp];

            float acc[4][4];
#pragma unroll
            for (int a = 0; a < 4; a++)
#pragma unroll
                for (int q = 0; q < 4; q++) acc[a][q] = 0.0f;

            for (int rr = 0; rr < 4; rr++) {
                const int k0c = rr * 64 + kg * 32;
#pragma unroll
                for (int i = 0; i < 2; i++) {
                    int f = t2 + i * 256;
                    int r = f >> 3;
                    int kq = (f & 7) << 2;
                    float4 va = *(const float4*)&x[((size_t)r * NS + s) * NE + k0c + kq];
                    *(uint4*)&Au[r * 36 + kq] = cvt4(va);
                    float4 vb = *(const float4*)&W[(size_t)(n0 + r) * NE + k0c + kq];
                    *(uint4*)&Bu[r * 36 + kq] = cvt4(vb);
                }
                __syncthreads();
                warp_mma_chunk<4>(Au, Bu, mg, ngb, l, acc);
                __syncthreads();
            }
            // kg-merge via gs, kg0 adds bias and stores
            if (kg == 1) {
#pragma unroll
                for (int nt = 0; nt < 4; nt++) {
                    int c = ngb + nt * 8 + ((l & 3) << 1);
                    int r = mg + (l >> 2);
                    gs[c * 65 + r]           = acc[nt][0];
                    gs[(c + 1) * 65 + r]     = acc[nt][1];
                    gs[c * 65 + r + 8]       = acc[nt][2];
                    gs[(c + 1) * 65 + r + 8] = acc[nt][3];
                }
            }
            __syncthreads();
            if (kg == 0) {
#pragma unroll
                for (int nt = 0; nt < 4; nt++) {
                    int c = ngb + nt * 8 + ((l & 3) << 1);
                    int r = mg + (l >> 2);
                    float b0 = bi[n0 + c] + bh[n0 + c];
                    float b1 = bi[n0 + c + 1] + bh[n0 + c + 1];
                    float2 o0, o1;
                    o0.x = acc[nt][0] + gs[c * 65 + r] + b0;
                    o0.y = acc[nt][1] + gs[(c + 1) * 65 + r] + b1;
                    o1.x = acc[nt][2] + gs[c * 65 + r + 8] + b0;
                    o1.y = acc[nt][3] + gs[(c + 1) * 65 + r + 8] + b1;
                    __stcs((float2*)&xo[((size_t)s * NB + r) * NG + n0 + c], o0);
                    __stcs((float2*)&xo[((size_t)s * NB + r + 8) * NG + n0 + c], o1);
                }
            }
            __syncthreads();
        }
    }
    gbar(&g_ctr[0], (unsigned)NBLK);
    if (bid >= RBLK) return;

    // ---------------- phase 2: the recurrence -------------------------------
    const int dir = bid >> 6;
    const int w   = bid & 63;
    const float* __restrict__ Whh = dir ? Whhb : Whhf;
    const float* __restrict__ Whr = dir ? Whrb : Whrf;
    const float* __restrict__ xg  = g_xg[dir];
    unsigned* ctr = &g_ctr[1 + dir];

    const int j0    = w << 4;            // gates: 16 hidden units
    const int p0    = (w & 15) << 4;     // proj: 16-col output tile
    const int kbase = (w >> 4) << 8;     // proj: K slice of 256

    float creg[2] = {0.0f, 0.0f};        // cell state in registers

    for (int t = 0; t < NS; t++) {
        const int par = t & 1;
        const float* __restrict__ h = g_h[par][dir];
        float* __restrict__ hn = g_h[par ^ 1][dir];
        const int s_eff = dir ? (NS - 1 - t) : t;

        if (tid < 256) hn[w * 256 + tid] = 0.0f;

        // prefetch xg for the cell update (mapping: m = tid + i*512)
        float xgi[2], xgf[2], xgg[2], xgo[2];
#pragma unroll
        for (int i = 0; i < 2; i++) {
            int m = tid + i * 512;
            int jl = m & 15, b = m >> 4;
            const float* p = &xg[((size_t)s_eff * NB + b) * NG + j0 + jl];
            xgi[i] = __ldcs(p);
            xgf[i] = __ldcs(p + 1024);
            xgg[i] = __ldcs(p + 2048);
            xgo[i] = __ldcs(p + 3072);
        }

        // ---- gates GEMM: 64b x 64c, K=256 (kg halves), tensor MMA ---------
        {
            const int ngb = (wi >> 2) << 5;
            float acc[4][4];
#pragma unroll
            for (int a = 0; a < 4; a++)
#pragma unroll
                for (int q = 0; q < 4; q++) acc[a][q] = 0.0f;

            for (int rr = 0; rr < 4; rr++) {
                const int k0c = rr * 64 + kg * 32;
#pragma unroll
                for (int i = 0; i < 2; i++) {
                    int f = t2 + i * 256;
                    int r = f >> 3;
                    int kq = (f & 7) << 2;
                    float4 va = __ldcg((const float4*)&h[r * NE + k0c + kq]);
                    *(uint4*)&Au[r * 36 + kq] = cvt4(va);
                    int g = ((r >> 4) << 10) + j0 + (r & 15);
                    float4 vb = *(const float4*)&Whh[(size_t)g * NE + k0c + kq];
                    *(uint4*)&Bu[r * 36 + kq] = cvt4(vb);
                }
                __syncthreads();
                warp_mma_chunk<4>(Au, Bu, mg, ngb, l, acc);
                __syncthreads();
            }
            if (kg == 1) {
#pragma unroll
                for (int nt = 0; nt < 4; nt++) {
                    int c = ngb + nt * 8 + ((l & 3) << 1);
                    int r = mg + (l >> 2);
                    gs[c * 65 + r]           = acc[nt][0];
                    gs[(c + 1) * 65 + r]     = acc[nt][1];
                    gs[c * 65 + r + 8]       = acc[nt][2];
                    gs[(c + 1) * 65 + r + 8] = acc[nt][3];
                }
            }
            __syncthreads();
            if (kg == 0) {
#pragma unroll
                for (int nt = 0; nt < 4; nt++) {
                    int c = ngb + nt * 8 + ((l & 3) << 1);
                    int r = mg + (l >> 2);
                    gs[c * 65 + r]           += acc[nt][0];
                    gs[(c + 1) * 65 + r]     += acc[nt][1];
                    gs[c * 65 + r + 8]       += acc[nt][2];
                    gs[(c + 1) * 65 + r + 8] += acc[nt][3];
                }
            }
            __syncthreads();
        }

        // ---- cell update (c in registers) ----------------------------------
#pragma unroll
        for (int i = 0; i < 2; i++) {
            int m = tid + i * 512;
            int jl = m & 15, b = m >> 4;
            float gi = gs[( 0 + jl) * 65 + b] + xgi[i];
            float gf = gs[(16 + jl) * 65 + b] + xgf[i];
            float gg = gs[(32 + jl) * 65 + b] + xgg[i];
            float go = gs[(48 + jl) * 65 + b] + xgo[i];
            float cn = sigf(gf) * creg[i] + sigf(gi) * tanh_f(gg);
            creg[i] = cn;
            g_a[dir][b * NH + j0 + jl] = sigf(go) * tanh_f(cn);
        }

        gbar(ctr, (unsigned)(2 * t + 1) * 64u);   // all a complete

        // ---- projection: hn[:, p0:p0+16] += a[:, kslice] @ Whr^T ----------
        {
            const int ngb = (wi >> 2) << 3;       // 0 or 8
            float acc[1][4];
            acc[0][0] = acc[0][1] = acc[0][2] = acc[0][3] = 0.0f;

            for (int rr = 0; rr < 4; rr++) {
                const int k0c = kbase + rr * 64 + kg * 32;
#pragma unroll
                for (int i = 0; i < 2; i++) {
                    int f = t2 + i * 256;
                    int r = f >> 3;
                    int kq = (f & 7) << 2;
                    float4 va = __ldcg((const float4*)&g_a[dir][r * NH + k0c + kq]);
                    *(uint4*)&Au[r * 36 + kq] = cvt4(va);
                }
                if (t2 < 128) {
                    int r = t2 >> 3;
                    int kq = (t2 & 7) << 2;
                    float4 vb = *(const float4*)&Whr[(size_t)(p0 + r) * NH + k0c + kq];
                    *(uint4*)&Bu[r * 36 + kq] = cvt4(vb);
                }
                __syncthreads();
                warp_mma_chunk<1>(Au, Bu, mg, ngb, l, acc);
                __syncthreads();
            }
            int c = ngb + ((l & 3) << 1);
            int r = mg + (l >> 2);
            if (kg == 1) {
                gs[c * 65 + r]           = acc[0][0];
                gs[(c + 1) * 65 + r]     = acc[0][1];
                gs[c * 65 + r + 8]       = acc[0][2];
                gs[(c + 1) * 65 + r + 8] = acc[0][3];
            }
            __syncthreads();
            if (kg == 0) {
                atomicAdd(&hn[r * NE + p0 + c],           acc[0][0] + gs[c * 65 + r]);
                atomicAdd(&hn[r * NE + p0 + c + 1],       acc[0][1] + gs[(c + 1) * 65 + r]);
                atomicAdd(&hn[(r + 8) * NE + p0 + c],     acc[0][2] + gs[c * 65 + r + 8]);
                atomicAdd(&hn[(r + 8) * NE + p0 + c + 1], acc[0][3] + gs[(c + 1) * 65 + r + 8]);
            }
        }

        gbar(ctr, (unsigned)(2 * t + 2) * 64u);   // h_next complete

        // ---- stream this step's h to output (batch w, coalesced) ----------
        if (tid < 256) {
            float v = __ldcg(&hn[w * 256 + tid]);
            out[((size_t)w * NS + s_eff) * (2 * NE) + dir * NE + tid] = v;
        }
    }
}

// ----------------------------- launcher -------------------------------------
extern "C" void kernel_launch(void* const* d_in, const int* in_sizes, int n_in,
                              void* d_out, int out_size) {
    (void)in_sizes; (void)n_in; (void)out_size;
    const float* x    = (const float*)d_in[0];
    const float* Wihf = (const float*)d_in[1];
    const float* Whhf = (const float*)d_in[2];
    const float* bihf = (const float*)d_in[3];
    const float* bhhf = (const float*)d_in[4];
    const float* Whrf = (const float*)d_in[5];
    const float* Wihb = (const float*)d_in[6];
    const float* Whhb = (const float*)d_in[7];
    const float* bihb = (const float*)d_in[8];
    const float* bhhb = (const float*)d_in[9];
    const float* Whrb = (const float*)d_in[10];
    float* out = (float*)d_out;

    init_kernel<<<64, 512>>>();
    lstm_kernel<<<NBLK, 512>>>(x, Wihf, Whhf, bihf, bhhf, Whrf,
                               Wihb, Whhb, bihb, bhhb, Whrb, out);
}

// round 10
// speedup vs baseline: 2.1427x; 1.1079x over previous
#include <cuda_runtime.h>
#include <cstddef>
#include <cstdint>

// Sizes: B=64, S=1024, E=256 (== proj dim), H=1024, G=4*H=4096
#define NB 64
#define NS 1024
#define NE 256
#define NH 1024
#define NG 4096
#define NBLK 148     // phase-1 blocks (all co-resident, 1/SM)
#define RBLK 128     // recurrence blocks (64 per direction)

// dynamic smem layout (float offsets)
#define WHH_OFF 0                 // 8 chunks x 64 rows x 36  = 18432
#define WHR_OFF 18432             // 8 chunks x 16 rows x 36  = 4608
#define ABUF_OFF 23040            // 2 kg x 2 pp x 64 x 36    = 9216
#define GS_OFF 32256              // 64 x 65                  = 4160
#define SMEM_FLOATS 36416         // 145664 bytes

// ---------------- device scratch (static: no runtime allocation) ------------
__device__ float g_xg[2][(size_t)NS * NB * NG];  // 2 x 1 GiB  xg [dir][s][b][g]
__device__ float g_h[2][2][NB * NE];             // [parity][dir][b*256+p]
__device__ float g_a[2][NB * NH];                // [dir][b*1024+j]
__device__ unsigned g_ctr[4];                    // [0]=grid, [1]=dir0, [2]=dir1

__device__ __forceinline__ float sigf(float x) { return 1.0f / (1.0f + __expf(-x)); }
__device__ __forceinline__ float tanh_f(float x) {
    float e = __expf(2.0f * x);
    return 1.0f - 2.0f / (e + 1.0f);
}

__device__ __forceinline__ uint4 cvt4(float4 v) {
    uint4 u;
    asm("cvt.rna.tf32.f32 %0, %1;" : "=r"(u.x) : "f"(v.x));
    asm("cvt.rna.tf32.f32 %0, %1;" : "=r"(u.y) : "f"(v.y));
    asm("cvt.rna.tf32.f32 %0, %1;" : "=r"(u.z) : "f"(v.z));
    asm("cvt.rna.tf32.f32 %0, %1;" : "=r"(u.w) : "f"(v.w));
    return u;
}

__device__ __forceinline__ void mma_tf32(float* acc,
                                         uint32_t a0, uint32_t a1, uint32_t a2, uint32_t a3,
                                         uint32_t b0, uint32_t b1) {
    asm volatile(
        "mma.sync.aligned.m16n8k8.row.col.f32.tf32.tf32.f32 "
        "{%0,%1,%2,%3}, {%4,%5,%6,%7}, {%8,%9}, {%0,%1,%2,%3};"
        : "+f"(acc[0]), "+f"(acc[1]), "+f"(acc[2]), "+f"(acc[3])
        : "r"(a0), "r"(a1), "r"(a2), "r"(a3), "r"(b0), "r"(b1));
}

// One 32-wide K chunk of warp-level MMA. A/B in smem row-major [row][36].
template <int NTS>
__device__ __forceinline__ void warp_mma_chunk(const uint32_t* __restrict__ Au,
                                               const uint32_t* __restrict__ Bu,
                                               int mg, int ngb, int l,
                                               float acc[][4]) {
#pragma unroll
    for (int ks = 0; ks < 4; ks++) {
        int k0 = ks * 8 + (l & 3);
        int ra = (mg + (l >> 2)) * 36 + k0;
        uint32_t a0 = Au[ra];
        uint32_t a1 = Au[ra + 8 * 36];
        uint32_t a2 = Au[ra + 4];
        uint32_t a3 = Au[ra + 8 * 36 + 4];
#pragma unroll
        for (int nt = 0; nt < NTS; nt++) {
            int rb = (ngb + nt * 8 + (l >> 2)) * 36 + k0;
            mma_tf32(acc[nt], a0, a1, a2, a3, Bu[rb], Bu[rb + 4]);
        }
    }
}

// A-side chunk fill: 64 rows x 32 k from global (cross-SM coherent) + tf32 cvt.
__device__ __forceinline__ void fillA(uint32_t* __restrict__ dst,
                                      const float* __restrict__ src,
                                      int k0, int rowstride, int t2) {
#pragma unroll
    for (int i = 0; i < 2; i++) {
        int f = t2 + i * 256;
        int r = f >> 3;
        int kq = (f & 7) << 2;
        float4 v = __ldcg((const float4*)&src[(size_t)r * rowstride + k0 + kq]);
        *(uint4*)&dst[r * 36 + kq] = cvt4(v);
    }
}

// Device-scope barrier: monotonic counter.
__device__ __forceinline__ void gbar(unsigned* c, unsigned target) {
    __syncthreads();
    if (threadIdx.x == 0) {
        __threadfence();
        atomicAdd(c, 1u);
        unsigned v;
        do {
            asm volatile("ld.global.acquire.gpu.u32 %0, [%1];"
                         : "=r"(v) : "l"(c) : "memory");
        } while (v < target);
    }
    __syncthreads();
}

// --------------------------- init: zero state + counters --------------------
__global__ void init_kernel() {
    int i = blockIdx.x * blockDim.x + threadIdx.x;
    if (i < 4) g_ctr[i] = 0u;
    if (i < 2 * NB * NE) (&g_h[0][0][0])[i] = 0.0f;
}

// --------------------------- the whole network ------------------------------
__global__ __launch_bounds__(512, 1) void lstm_kernel(
    const float* __restrict__ x,
    const float* __restrict__ Wihf, const float* __restrict__ Whhf,
    const float* __restrict__ bihf, const float* __restrict__ bhhf,
    const float* __restrict__ Whrf,
    const float* __restrict__ Wihb, const float* __restrict__ Whhb,
    const float* __restrict__ bihb, const float* __restrict__ bhhb,
    const float* __restrict__ Whrb,
    float* __restrict__ out)
{
    extern __shared__ __align__(16) float pool[];

    const int bid = blockIdx.x;
    const int tid = threadIdx.x;
    const int kg  = tid >> 8;          // K-group 0/1
    const int t2  = tid & 255;
    const int l   = tid & 31;
    const int wi  = t2 >> 5;           // warp-in-group 0..7
    const int mg  = (wi & 3) << 4;     // m16 group row base
    float* gs = pool + GS_OFF;

    // ---------------- phase 1: xg = x @ W_ih^T + (b_ih + b_hh) -------------
    {
        uint32_t* Au = (uint32_t*)(pool + kg * 2304);
        uint32_t* Bu = (uint32_t*)(pool + 4608 + kg * 2304);
        const int ngb = (wi >> 2) << 5;          // 0 or 32
        const int total_tiles = 2 * 64 * NS;
        for (int tile = bid; tile < total_tiles; tile += NBLK) {
            const int s      = tile & (NS - 1);
            const int stripe = tile >> 10;        // 0..127
            const int dp     = stripe >> 6;
            const int n0     = (stripe & 63) << 6;
            const float* __restrict__ W  = dp ? Wihb : Wihf;
            const float* __restrict__ bi = dp ? bihb : bihf;
            const float* __restrict__ bh = dp ? bhhb : bhhf;
            float* __restrict__ xo = g_xg[dp];

            float acc[4][4];
#pragma unroll
            for (int a = 0; a < 4; a++)
#pragma unroll
                for (int q = 0; q < 4; q++) acc[a][q] = 0.0f;

            for (int rr = 0; rr < 4; rr++) {
                const int k0c = rr * 64 + kg * 32;
#pragma unroll
                for (int i = 0; i < 2; i++) {
                    int f = t2 + i * 256;
                    int r = f >> 3;
                    int kq = (f & 7) << 2;
                    float4 va = *(const float4*)&x[((size_t)r * NS + s) * NE + k0c + kq];
                    *(uint4*)&Au[r * 36 + kq] = cvt4(va);
                    float4 vb = *(const float4*)&W[(size_t)(n0 + r) * NE + k0c + kq];
                    *(uint4*)&Bu[r * 36 + kq] = cvt4(vb);
                }
                __syncthreads();
                warp_mma_chunk<4>(Au, Bu, mg, ngb, l, acc);
                __syncthreads();
            }
            if (kg == 1) {
#pragma unroll
                for (int nt = 0; nt < 4; nt++) {
                    int c = ngb + nt * 8 + ((l & 3) << 1);
                    int r = mg + (l >> 2);
                    gs[c * 65 + r]           = acc[nt][0];
                    gs[(c + 1) * 65 + r]     = acc[nt][1];
                    gs[c * 65 + r + 8]       = acc[nt][2];
                    gs[(c + 1) * 65 + r + 8] = acc[nt][3];
                }
            }
            __syncthreads();
            if (kg == 0) {
#pragma unroll
                for (int nt = 0; nt < 4; nt++) {
                    int c = ngb + nt * 8 + ((l & 3) << 1);
                    int r = mg + (l >> 2);
                    float b0 = bi[n0 + c] + bh[n0 + c];
                    float b1 = bi[n0 + c + 1] + bh[n0 + c + 1];
                    float2 o0, o1;
                    o0.x = acc[nt][0] + gs[c * 65 + r] + b0;
                    o0.y = acc[nt][1] + gs[(c + 1) * 65 + r] + b1;
                    o1.x = acc[nt][2] + gs[c * 65 + r + 8] + b0;
                    o1.y = acc[nt][3] + gs[(c + 1) * 65 + r + 8] + b1;
                    __stcs((float2*)&xo[((size_t)s * NB + r) * NG + n0 + c], o0);
                    __stcs((float2*)&xo[((size_t)s * NB + r + 8) * NG + n0 + c], o1);
                }
            }
            __syncthreads();
        }
    }
    gbar(&g_ctr[0], (unsigned)NBLK);
    if (bid >= RBLK) return;

    // ---------------- phase 2: the recurrence -------------------------------
    const int dir = bid >> 6;
    const int w   = bid & 63;
    const float* __restrict__ Whh = dir ? Whhb : Whhf;
    const float* __restrict__ Whr = dir ? Whrb : Whrf;
    const float* __restrict__ xg  = g_xg[dir];
    unsigned* ctr = &g_ctr[1 + dir];

    const int j0    = w << 4;            // gates: 16 hidden units
    const int p0    = (w & 15) << 4;     // proj: 16-col output tile
    const int kbase = (w >> 4) << 8;     // proj: K slice of 256

    uint32_t* WhhS = (uint32_t*)(pool + WHH_OFF);
    uint32_t* WhrS = (uint32_t*)(pool + WHR_OFF);
    uint32_t* Ab   = (uint32_t*)(pool + ABUF_OFF) + kg * 2 * 2304;

    // ---- load weights into smem ONCE (pre-converted tf32) ------------------
#pragma unroll
    for (int ci = 0; ci < 8; ci++) {
        int r = tid >> 3;                // 0..63
        int kq = (tid & 7) << 2;
        int g = ((r >> 4) << 10) + j0 + (r & 15);
        float4 wv = *(const float4*)&Whh[(size_t)g * NE + ci * 32 + kq];
        *(uint4*)&WhhS[ci * 2304 + r * 36 + kq] = cvt4(wv);
    }
    if (tid < 128) {
#pragma unroll
        for (int ci = 0; ci < 8; ci++) {
            int r = tid >> 3;            // 0..15
            int kq = (tid & 7) << 2;
            float4 wv = *(const float4*)&Whr[(size_t)(p0 + r) * NH + kbase + ci * 32 + kq];
            *(uint4*)&WhrS[ci * 576 + r * 36 + kq] = cvt4(wv);
        }
    }
    __syncthreads();

    float creg[2] = {0.0f, 0.0f};        // cell state in registers

    for (int t = 0; t < NS; t++) {
        const int par = t & 1;
        const float* __restrict__ h = g_h[par][dir];
        float* __restrict__ hn = g_h[par ^ 1][dir];
        const int s_eff = dir ? (NS - 1 - t) : t;

        if (tid < 256) hn[w * 256 + tid] = 0.0f;

        // prefetch xg for the cell update (mapping: m = tid + i*512)
        float xgi[2], xgf[2], xgg[2], xgo[2];
#pragma unroll
        for (int i = 0; i < 2; i++) {
            int m = tid + i * 512;
            int jl = m & 15, b = m >> 4;
            const float* p = &xg[((size_t)s_eff * NB + b) * NG + j0 + jl];
            xgi[i] = __ldcs(p);
            xgf[i] = __ldcs(p + 1024);
            xgg[i] = __ldcs(p + 2048);
            xgo[i] = __ldcs(p + 3072);
        }

        // ---- gates GEMM: 64b x 64c, K=256 (kg halves), resident Whh -------
        {
            const int ngb = (wi >> 2) << 5;
            float acc[4][4];
#pragma unroll
            for (int a = 0; a < 4; a++)
#pragma unroll
                for (int q = 0; q < 4; q++) acc[a][q] = 0.0f;

            fillA(Ab, h, kg * 128, NE, t2);             // chunk 0
            __syncthreads();
#pragma unroll
            for (int rr = 0; rr < 4; rr++) {
                if (rr < 3)
                    fillA(Ab + ((rr + 1) & 1) * 2304, h, kg * 128 + (rr + 1) * 32, NE, t2);
                warp_mma_chunk<4>(Ab + (rr & 1) * 2304,
                                  WhhS + (kg * 4 + rr) * 2304, mg, ngb, l, acc);
                __syncthreads();
            }
            if (kg == 1) {
#pragma unroll
                for (int nt = 0; nt < 4; nt++) {
                    int c = ngb + nt * 8 + ((l & 3) << 1);
                    int r = mg + (l >> 2);
                    gs[c * 65 + r]           = acc[nt][0];
                    gs[(c + 1) * 65 + r]     = acc[nt][1];
                    gs[c * 65 + r + 8]       = acc[nt][2];
                    gs[(c + 1) * 65 + r + 8] = acc[nt][3];
                }
            }
            __syncthreads();
            if (kg == 0) {
#pragma unroll
                for (int nt = 0; nt < 4; nt++) {
                    int c = ngb + nt * 8 + ((l & 3) << 1);
                    int r = mg + (l >> 2);
                    gs[c * 65 + r]           += acc[nt][0];
                    gs[(c + 1) * 65 + r]     += acc[nt][1];
                    gs[c * 65 + r + 8]       += acc[nt][2];
                    gs[(c + 1) * 65 + r + 8] += acc[nt][3];
                }
            }
            __syncthreads();
        }

        // ---- cell update (c in registers) ----------------------------------
#pragma unroll
        for (int i = 0; i < 2; i++) {
            int m = tid + i * 512;
            int jl = m & 15, b = m >> 4;
            float gi = gs[( 0 + jl) * 65 + b] + xgi[i];
            float gf = gs[(16 + jl) * 65 + b] + xgf[i];
            float gg = gs[(32 + jl) * 65 + b] + xgg[i];
            float go = gs[(48 + jl) * 65 + b] + xgo[i];
            float cn = sigf(gf) * creg[i] + sigf(gi) * tanh_f(gg);
            creg[i] = cn;
            g_a[dir][b * NH + j0 + jl] = sigf(go) * tanh_f(cn);
        }

        gbar(ctr, (unsigned)(2 * t + 1) * 64u);   // all a complete

        // ---- projection: hn[:, p0:p0+16] += a[:, kslice] @ Whr^T ----------
        {
            const int ngb = (wi >> 2) << 3;       // 0 or 8
            float acc[1][4];
            acc[0][0] = acc[0][1] = acc[0][2] = acc[0][3] = 0.0f;

            fillA(Ab, g_a[dir], kbase + kg * 128, NH, t2);    // chunk 0
            __syncthreads();
#pragma unroll
            for (int rr = 0; rr < 4; rr++) {
                if (rr < 3)
                    fillA(Ab + ((rr + 1) & 1) * 2304, g_a[dir],
                          kbase + kg * 128 + (rr + 1) * 32, NH, t2);
                warp_mma_chunk<1>(Ab + (rr & 1) * 2304,
                                  WhrS + (kg * 4 + rr) * 576, mg, ngb, l, acc);
                __syncthreads();
            }
            int c = ngb + ((l & 3) << 1);
            int r = mg + (l >> 2);
            if (kg == 1) {
                gs[c * 65 + r]           = acc[0][0];
                gs[(c + 1) * 65 + r]     = acc[0][1];
                gs[c * 65 + r + 8]       = acc[0][2];
                gs[(c + 1) * 65 + r + 8] = acc[0][3];
            }
            __syncthreads();
            if (kg == 0) {
                atomicAdd(&hn[r * NE + p0 + c],           acc[0][0] + gs[c * 65 + r]);
                atomicAdd(&hn[r * NE + p0 + c + 1],       acc[0][1] + gs[(c + 1) * 65 + r]);
                atomicAdd(&hn[(r + 8) * NE + p0 + c],     acc[0][2] + gs[c * 65 + r + 8]);
                atomicAdd(&hn[(r + 8) * NE + p0 + c + 1], acc[0][3] + gs[(c + 1) * 65 + r + 8]);
            }
        }

        gbar(ctr, (unsigned)(2 * t + 2) * 64u);   // h_next complete

        // ---- stream this step's h to output (batch w, coalesced) ----------
        if (tid < 256) {
            float v = __ldcg(&hn[w * 256 + tid]);
            out[((size_t)w * NS + s_eff) * (2 * NE) + dir * NE + tid] = v;
        }
    }
}

// ----------------------------- launcher -------------------------------------
extern "C" void kernel_launch(void* const* d_in, const int* in_sizes, int n_in,
                              void* d_out, int out_size) {
    (void)in_sizes; (void)n_in; (void)out_size;
    const float* x    = (const float*)d_in[0];
    const float* Wihf = (const float*)d_in[1];
    const float* Whhf = (const float*)d_in[2];
    const float* bihf = (const float*)d_in[3];
    const float* bhhf = (const float*)d_in[4];
    const float* Whrf = (const float*)d_in[5];
    const float* Wihb = (const float*)d_in[6];
    const float* Whhb = (const float*)d_in[7];
    const float* bihb = (const float*)d_in[8];
    const float* bhhb = (const float*)d_in[9];
    const float* Whrb = (const float*)d_in[10];
    float* out = (float*)d_out;

    cudaFuncSetAttribute(lstm_kernel,
                         cudaFuncAttributeMaxDynamicSharedMemorySize,
                         SMEM_FLOATS * 4);
    init_kernel<<<64, 512>>>();
    lstm_kernel<<<NBLK, 512, SMEM_FLOATS * 4>>>(
        x, Wihf, Whhf, bihf, bhhf, Whrf,
        Wihb, Whhb, bihb, bhhb, Whrb, out);
}

// round 11
// speedup vs baseline: 2.2674x; 1.0582x over previous
#include <cuda_runtime.h>
#include <cstddef>
#include <cstdint>

// Sizes: B=64, S=1024, E=256 (== proj dim), H=1024, G=4*H=4096
#define NB 64
#define NS 1024
#define NE 256
#define NH 1024
#define NG 4096
#define RBLK 128     // blocks (64 per direction), 1/SM

// dynamic smem layout (float offsets)
#define WHH_OFF 0                 // 8 chunks x 64 rows x 36     = 18432
#define WHR_OFF 18432             // 16 cols x 1028              = 16448
#define TRANS_OFF 34880           // max(gates 2x2x2304, proj 16x1028) = 16448
#define GS_OFF 51328              // max(64x65, 256x17)          = 4352
#define SMEM_FLOATS 55680         // 222720 bytes

// ---------------- device scratch (static: no runtime allocation) ------------
__device__ float g_xg[2][(size_t)NS * NB * NG];  // 2 x 1 GiB  xg [dir][s][b][g]
__device__ float g_xq[(size_t)NB * NS * NE];     // 64 MB  x rounded to tf32
__device__ float g_hq[2][2][NB * NE];            // [parity][dir] rounded h
__device__ float g_a[2][NB * NH];                // [dir][b*1024+j] rounded
__device__ unsigned g_ctr[4];                    // [0]=grid, [1]=dir0, [2]=dir1

__device__ __forceinline__ float sigf(float x) { return 1.0f / (1.0f + __expf(-x)); }
__device__ __forceinline__ float tanh_f(float x) {
    float e = __expf(2.0f * x);
    return 1.0f - 2.0f / (e + 1.0f);
}

__device__ __forceinline__ uint4 cvt4(float4 v) {
    uint4 u;
    asm("cvt.rna.tf32.f32 %0, %1;" : "=r"(u.x) : "f"(v.x));
    asm("cvt.rna.tf32.f32 %0, %1;" : "=r"(u.y) : "f"(v.y));
    asm("cvt.rna.tf32.f32 %0, %1;" : "=r"(u.z) : "f"(v.z));
    asm("cvt.rna.tf32.f32 %0, %1;" : "=r"(u.w) : "f"(v.w));
    return u;
}
__device__ __forceinline__ float cvt1(float v) {
    uint32_t u;
    asm("cvt.rna.tf32.f32 %0, %1;" : "=r"(u) : "f"(v));
    return __uint_as_float(u);
}

__device__ __forceinline__ void mma_tf32(float* acc,
                                         uint32_t a0, uint32_t a1, uint32_t a2, uint32_t a3,
                                         uint32_t b0, uint32_t b1) {
    asm volatile(
        "mma.sync.aligned.m16n8k8.row.col.f32.tf32.tf32.f32 "
        "{%0,%1,%2,%3}, {%4,%5,%6,%7}, {%8,%9}, {%0,%1,%2,%3};"
        : "+f"(acc[0]), "+f"(acc[1]), "+f"(acc[2]), "+f"(acc[3])
        : "r"(a0), "r"(a1), "r"(a2), "r"(a3), "r"(b0), "r"(b1));
}

// One 32-wide K chunk of warp-level MMA. A/B in smem row-major [row][36].
template <int NTS>
__device__ __forceinline__ void warp_mma_chunk(const uint32_t* __restrict__ Au,
                                               const uint32_t* __restrict__ Bu,
                                               int mg, int ngb, int l,
                                               float acc[][4]) {
#pragma unroll
    for (int ks = 0; ks < 4; ks++) {
        int k0 = ks * 8 + (l & 3);
        int ra = (mg + (l >> 2)) * 36 + k0;
        uint32_t a0 = Au[ra];
        uint32_t a1 = Au[ra + 8 * 36];
        uint32_t a2 = Au[ra + 4];
        uint32_t a3 = Au[ra + 8 * 36 + 4];
#pragma unroll
        for (int nt = 0; nt < NTS; nt++) {
            int rb = (ngb + nt * 8 + (l >> 2)) * 36 + k0;
            mma_tf32(acc[nt], a0, a1, a2, a3, Bu[rb], Bu[rb + 4]);
        }
    }
}

// A-side chunk fill, raw copy (source already tf32-rounded): 64 rows x 32 k.
__device__ __forceinline__ void fillA_raw(float* __restrict__ dst,
                                          const float* __restrict__ src,
                                          int k0, size_t rowstride, int t2) {
#pragma unroll
    for (int i = 0; i < 2; i++) {
        int f = t2 + i * 256;
        int r = f >> 3;
        int kq = (f & 7) << 2;
        float4 v = __ldcg((const float4*)&src[(size_t)r * rowstride + k0 + kq]);
        *(float4*)&dst[r * 36 + kq] = v;
    }
}

// Device-scope barrier: monotonic counter.
__device__ __forceinline__ void gbar(unsigned* c, unsigned target) {
    __syncthreads();
    if (threadIdx.x == 0) {
        __threadfence();
        atomicAdd(c, 1u);
        unsigned v;
        do {
            asm volatile("ld.global.acquire.gpu.u32 %0, [%1];"
                         : "=r"(v) : "l"(c) : "memory");
        } while (v < target);
    }
    __syncthreads();
}

// --------------------------- init: zero state + counters --------------------
__global__ void init_kernel() {
    int i = blockIdx.x * blockDim.x + threadIdx.x;   // 128 x 512 = 65536
    if (i < 4) g_ctr[i] = 0u;
    if (i < 2 * 2 * NB * NE) (&g_hq[0][0][0])[i] = 0.0f;
}

// --------------------------- the whole network ------------------------------
__global__ __launch_bounds__(512, 1) void lstm_kernel(
    const float* __restrict__ x,
    const float* __restrict__ Wihf, const float* __restrict__ Whhf,
    const float* __restrict__ bihf, const float* __restrict__ bhhf,
    const float* __restrict__ Whrf,
    const float* __restrict__ Wihb, const float* __restrict__ Whhb,
    const float* __restrict__ bihb, const float* __restrict__ bhhb,
    const float* __restrict__ Whrb,
    float* __restrict__ out)
{
    extern __shared__ __align__(16) float pool[];

    const int bid = blockIdx.x;
    const int tid = threadIdx.x;
    const int kg  = tid >> 8;          // K-group 0/1
    const int t2  = tid & 255;
    const int l   = tid & 31;
    const int wid = tid >> 5;          // warp 0..15
    const int wi  = t2 >> 5;           // warp-in-group 0..7
    const int mg  = (wi & 3) << 4;     // m16 group row base
    const int dir = bid >> 6;
    float* gs = pool + GS_OFF;

    // ---------------- phase 0: round x into g_xq ----------------------------
    {
        const size_t n4 = (size_t)NB * NS * NE / 4;
        for (size_t i4 = (size_t)bid * 512 + tid; i4 < n4; i4 += (size_t)RBLK * 512) {
            float4 v = ((const float4*)x)[i4];
            *(uint4*)&((float4*)g_xq)[i4] = cvt4(v);
        }
    }
    gbar(&g_ctr[0], (unsigned)RBLK);

    // ---------------- phase 1: xg = x @ W_ih^T + (b_ih + b_hh) -------------
    // Block owns one 64-wide gate stripe (stripe-resident W in smem), loops s.
    {
        const int n0 = (bid & 63) << 6;
        const float* __restrict__ W  = dir ? Wihb : Wihf;
        const float* __restrict__ bi = dir ? bihb : bihf;
        const float* __restrict__ bh = dir ? bhhb : bhhf;
        float* __restrict__ xo = g_xg[dir];
        uint32_t* WS = (uint32_t*)(pool + WHH_OFF);
        float* Ab = pool + TRANS_OFF + kg * 2 * 2304;
        const int ngb = (wi >> 2) << 5;          // 0 or 32

        // load + cvt stripe weights once: 8 chunks x 64 rows x 32 k
#pragma unroll
        for (int ci = 0; ci < 8; ci++) {
            int r = tid >> 3;
            int kq = (tid & 7) << 2;
            float4 wv = *(const float4*)&W[(size_t)(n0 + r) * NE + ci * 32 + kq];
            *(uint4*)&WS[ci * 2304 + r * 36 + kq] = cvt4(wv);
        }
        // bias per thread (kg0 merge lanes)
        float bias0[4], bias1[4];
#pragma unroll
        for (int nt = 0; nt < 4; nt++) {
            int c = ngb + nt * 8 + ((l & 3) << 1);
            bias0[nt] = bi[n0 + c] + bh[n0 + c];
            bias1[nt] = bi[n0 + c + 1] + bh[n0 + c + 1];
        }
        __syncthreads();

        for (int s = 0; s < NS; s++) {
            const float* xsrc = g_xq + (size_t)s * NE;
            float acc[4][4];
#pragma unroll
            for (int a = 0; a < 4; a++)
#pragma unroll
                for (int q = 0; q < 4; q++) acc[a][q] = 0.0f;

            fillA_raw(Ab, xsrc, kg * 128, (size_t)NS * NE, t2);
            __syncthreads();
#pragma unroll
            for (int rr = 0; rr < 4; rr++) {
                if (rr < 3)
                    fillA_raw(Ab + ((rr + 1) & 1) * 2304, xsrc,
                              kg * 128 + (rr + 1) * 32, (size_t)NS * NE, t2);
                warp_mma_chunk<4>((uint32_t*)(Ab + (rr & 1) * 2304),
                                  WS + (kg * 4 + rr) * 2304, mg, ngb, l, acc);
                __syncthreads();
            }
            if (kg == 1) {
#pragma unroll
                for (int nt = 0; nt < 4; nt++) {
                    int c = ngb + nt * 8 + ((l & 3) << 1);
                    int r = mg + (l >> 2);
                    gs[c * 65 + r]           = acc[nt][0];
                    gs[(c + 1) * 65 + r]     = acc[nt][1];
                    gs[c * 65 + r + 8]       = acc[nt][2];
                    gs[(c + 1) * 65 + r + 8] = acc[nt][3];
                }
            }
            __syncthreads();
            if (kg == 0) {
#pragma unroll
                for (int nt = 0; nt < 4; nt++) {
                    int c = ngb + nt * 8 + ((l & 3) << 1);
                    int r = mg + (l >> 2);
                    float2 o0, o1;
                    o0.x = acc[nt][0] + gs[c * 65 + r] + bias0[nt];
                    o0.y = acc[nt][1] + gs[(c + 1) * 65 + r] + bias1[nt];
                    o1.x = acc[nt][2] + gs[c * 65 + r + 8] + bias0[nt];
                    o1.y = acc[nt][3] + gs[(c + 1) * 65 + r + 8] + bias1[nt];
                    __stcs((float2*)&xo[((size_t)s * NB + r) * NG + n0 + c], o0);
                    __stcs((float2*)&xo[((size_t)s * NB + r + 8) * NG + n0 + c], o1);
                }
            }
            __syncthreads();
        }
    }
    gbar(&g_ctr[0], 2u * RBLK);

    // ---------------- phase 2: the recurrence -------------------------------
    const int u = bid & 63;
    const float* __restrict__ Whh = dir ? Whhb : Whhf;
    const float* __restrict__ Whr = dir ? Whrb : Whrf;
    const float* __restrict__ xg  = g_xg[dir];
    unsigned* ctr = &g_ctr[1 + dir];

    const int j0 = u << 4;                     // gates: 16 hidden units
    const int b0 = (u >> 4) << 4;              // proj: 16-batch tile
    const int p0 = (u & 15) << 4;              // proj: 16-col tile

    uint32_t* WhhS = (uint32_t*)(pool + WHH_OFF);
    uint32_t* WhrS = (uint32_t*)(pool + WHR_OFF);
    float* Ab = pool + TRANS_OFF + kg * 2 * 2304;   // gates A (aliases proj AP)
    float* AP = pool + TRANS_OFF;                    // proj A [r][1028]

    // ---- load weights into smem ONCE (pre-converted tf32) ------------------
#pragma unroll
    for (int ci = 0; ci < 8; ci++) {
        int r = tid >> 3;
        int kq = (tid & 7) << 2;
        int g = ((r >> 4) << 10) + j0 + (r & 15);
        float4 wv = *(const float4*)&Whh[(size_t)g * NE + ci * 32 + kq];
        *(uint4*)&WhhS[ci * 2304 + r * 36 + kq] = cvt4(wv);
    }
#pragma unroll
    for (int i = 0; i < 8; i++) {
        int f = tid + i * 512;                 // 0..4095
        int c = f >> 8;                        // 0..15
        int kq = (f & 255) << 2;               // 0..1020
        float4 wv = *(const float4*)&Whr[(size_t)(p0 + c) * NH + kq];
        *(uint4*)&WhrS[c * 1028 + kq] = cvt4(wv);
    }
    __syncthreads();

    float creg[2] = {0.0f, 0.0f};              // cell state in registers

    for (int t = 0; t < NS; t++) {
        const int par = t & 1;
        const float* __restrict__ h = g_hq[par][dir];
        const int s_eff = dir ? (NS - 1 - t) : t;

        // prefetch xg for the cell update (mapping: m = tid + i*512)
        float xgi[2], xgf[2], xgg[2], xgo[2];
#pragma unroll
        for (int i = 0; i < 2; i++) {
            int m = tid + i * 512;
            int jl = m & 15, b = m >> 4;
            const float* p = &xg[((size_t)s_eff * NB + b) * NG + j0 + jl];
            xgi[i] = __ldcs(p);
            xgf[i] = __ldcs(p + 1024);
            xgg[i] = __ldcs(p + 2048);
            xgo[i] = __ldcs(p + 3072);
        }

        // ---- gates GEMM: 64b x 64c, K=256 (kg halves), resident Whh -------
        {
            const int ngb = (wi >> 2) << 5;
            float acc[4][4];
#pragma unroll
            for (int a = 0; a < 4; a++)
#pragma unroll
                for (int q = 0; q < 4; q++) acc[a][q] = 0.0f;

            fillA_raw(Ab, h, kg * 128, NE, t2);
            __syncthreads();
#pragma unroll
            for (int rr = 0; rr < 4; rr++) {
                if (rr < 3)
                    fillA_raw(Ab + ((rr + 1) & 1) * 2304, h,
                              kg * 128 + (rr + 1) * 32, NE, t2);
                warp_mma_chunk<4>((uint32_t*)(Ab + (rr & 1) * 2304),
                                  WhhS + (kg * 4 + rr) * 2304, mg, ngb, l, acc);
                __syncthreads();
            }
            if (kg == 1) {
#pragma unroll
                for (int nt = 0; nt < 4; nt++) {
                    int c = ngb + nt * 8 + ((l & 3) << 1);
                    int r = mg + (l >> 2);
                    gs[c * 65 + r]           = acc[nt][0];
                    gs[(c + 1) * 65 + r]     = acc[nt][1];
                    gs[c * 65 + r + 8]       = acc[nt][2];
                    gs[(c + 1) * 65 + r + 8] = acc[nt][3];
                }
            }
            __syncthreads();
            if (kg == 0) {
#pragma unroll
                for (int nt = 0; nt < 4; nt++) {
                    int c = ngb + nt * 8 + ((l & 3) << 1);
                    int r = mg + (l >> 2);
                    gs[c * 65 + r]           += acc[nt][0];
                    gs[(c + 1) * 65 + r]     += acc[nt][1];
                    gs[c * 65 + r + 8]       += acc[nt][2];
                    gs[(c + 1) * 65 + r + 8] += acc[nt][3];
                }
            }
            __syncthreads();
        }

        // ---- cell update (c in registers), rounded a to global ------------
#pragma unroll
        for (int i = 0; i < 2; i++) {
            int m = tid + i * 512;
            int jl = m & 15, b = m >> 4;
            float gi = gs[( 0 + jl) * 65 + b] + xgi[i];
            float gf = gs[(16 + jl) * 65 + b] + xgf[i];
            float gg = gs[(32 + jl) * 65 + b] + xgg[i];
            float go = gs[(48 + jl) * 65 + b] + xgo[i];
            float cn = sigf(gf) * creg[i] + sigf(gi) * tanh_f(gg);
            creg[i] = cn;
            g_a[dir][b * NH + j0 + jl] = cvt1(sigf(go) * tanh_f(cn));
        }

        gbar(ctr, (unsigned)(2 * t + 1) * 64u);   // all a complete

        // ---- projection: h[b0:b0+16, p0:p0+16] = a @ Whr^T (full K=1024) --
        {
            // fill A: 16 rows x 1024 k, raw (a pre-rounded)
#pragma unroll
            for (int i = 0; i < 8; i++) {
                int f = tid + i * 512;
                int r = f >> 8;
                int kq = (f & 255) << 2;
                float4 v = __ldcg((const float4*)&g_a[dir][(size_t)(b0 + r) * NH + kq]);
                *(float4*)&AP[r * 1028 + kq] = v;
            }
            __syncthreads();

            uint32_t* APu = (uint32_t*)AP;
            float pacc[2][4];
#pragma unroll
            for (int nt = 0; nt < 2; nt++)
#pragma unroll
                for (int q = 0; q < 4; q++) pacc[nt][q] = 0.0f;

            const int kw = wid * 64;               // this warp's K slice
#pragma unroll
            for (int ks = 0; ks < 8; ks++) {
                int k0 = kw + ks * 8 + (l & 3);
                int ra = (l >> 2) * 1028 + k0;
                uint32_t a0 = APu[ra];
                uint32_t a1 = APu[ra + 8 * 1028];
                uint32_t a2 = APu[ra + 4];
                uint32_t a3 = APu[ra + 8 * 1028 + 4];
#pragma unroll
                for (int nt = 0; nt < 2; nt++) {
                    int rb = (nt * 8 + (l >> 2)) * 1028 + k0;
                    mma_tf32(pacc[nt], a0, a1, a2, a3, WhrS[rb], WhrS[rb + 4]);
                }
            }
            // partials -> smem [ (r*16+c)*17 + warp ]
#pragma unroll
            for (int nt = 0; nt < 2; nt++) {
                int c0 = nt * 8 + ((l & 3) << 1);
                int r0 = l >> 2;
                gs[(r0 * 16 + c0) * 17 + wid]           = pacc[nt][0];
                gs[(r0 * 16 + c0 + 1) * 17 + wid]       = pacc[nt][1];
                gs[((r0 + 8) * 16 + c0) * 17 + wid]     = pacc[nt][2];
                gs[((r0 + 8) * 16 + c0 + 1) * 17 + wid] = pacc[nt][3];
            }
            __syncthreads();

            // reduce 16 partials, write out + rounded h
            if (tid < 256) {
                float v = 0.0f;
#pragma unroll
                for (int ww = 0; ww < 16; ww++) v += gs[tid * 17 + ww];
                int b = b0 + (tid >> 4);
                int p = p0 + (tid & 15);
                out[((size_t)b * NS + s_eff) * (2 * NE) + dir * NE + p] = v;
                g_hq[par ^ 1][dir][b * NE + p] = cvt1(v);
            }
        }

        gbar(ctr, (unsigned)(2 * t + 2) * 64u);   // h_next complete
    }
}

// ----------------------------- launcher -------------------------------------
extern "C" void kernel_launch(void* const* d_in, const int* in_sizes, int n_in,
                              void* d_out, int out_size) {
    (void)in_sizes; (void)n_in; (void)out_size;
    const float* x    = (const float*)d_in[0];
    const float* Wihf = (const float*)d_in[1];
    const float* Whhf = (const float*)d_in[2];
    const float* bihf = (const float*)d_in[3];
    const float* bhhf = (const float*)d_in[4];
    const float* Whrf = (const float*)d_in[5];
    const float* Wihb = (const float*)d_in[6];
    const float* Whhb = (const float*)d_in[7];
    const float* bihb = (const float*)d_in[8];
    const float* bhhb = (const float*)d_in[9];
    const float* Whrb = (const float*)d_in[10];
    float* out = (float*)d_out;

    cudaFuncSetAttribute(lstm_kernel,
                         cudaFuncAttributeMaxDynamicSharedMemorySize,
                         SMEM_FLOATS * 4);
    init_kernel<<<128, 512>>>();
    lstm_kernel<<<RBLK, 512, SMEM_FLOATS * 4>>>(
        x, Wihf, Whhf, bihf, bhhf, Whrf,
        Wihb, Whhb, bihb, bhhb, Whrb, out);
}